// round 13
// baseline (speedup 1.0000x reference)
#include <cuda_runtime.h>
#include <cuda_fp16.h>
#include <cstdint>

#define NN   100000
#define EE   200000
#define GG   4096
#define HID  512
#define LAYERS 4
#define HEADS 8
#define BASES 8
#define NAGG 3
#define FH   64
#define COMBC 192
#define COMBP 256
#define NCAT 704                   // 512 bases + 192 comb (no padding)
#define DESC 200
#define CAT  (128 + DESC)          // 328
#define EPSBN 1e-5f

// 4-stage GEMM smem: per stage As 128x40 halves (10240B) + Bs 32x136 halves (8704B)
#define STG_BYTES 18944
#define G_SMEM (4*STG_BYTES)       // 75776

// ---------------- scratch (static device allocations; no cudaMalloc) ----------------
__device__ __half d_h     [(long)NN*HID];      // residual stream, fp16
__device__ __half d_t     [(long)NN*HID];      // conv output (pre-BN), fp16
__device__ __half d_bases [(long)NN*HID];
__device__ float  d_comb  [(long)NN*COMBP];    // row stride 256, cols [0,192) valid
__device__ float  d_part  [256*2*HID];
__device__ float  d_scale [HID];
__device__ float  d_shift [HID];
__device__ float  d_pool  [(long)GG*HID];
__device__ float  d_z1    [(long)GG*256];
__device__ float  d_z2    [(long)GG*128];
__device__ float  d_zc    [(long)GG*CAT];
__device__ float  d_z3    [(long)GG*128];
__device__ __half d_wcat  [(long)LAYERS*HID*NCAT];   // [l][k][n]
// CSR
__device__ int d_deg [NN];
__device__ int d_off [NN+1];
__device__ int d_cur [NN];
__device__ int d_csrc[EE];
__device__ int d_bsum[256];

// ---------------- lin1 (writes fp16 t) ----------------------------------------------
__global__ void k_lin1(const float* __restrict__ x, const float* __restrict__ W,
                       __half* __restrict__ out) {
    int n = blockIdx.x;
    __shared__ float xs[27];
    int tid = threadIdx.x;   // 256
    if (tid < 27) xs[tid] = x[n*27 + tid];
    __syncthreads();
    int c = tid * 2;
    float a0 = 0.f, a1 = 0.f;
    #pragma unroll
    for (int k = 0; k < 27; k++) {
        float xv = xs[k];
        a0 += xv * W[k*HID + c];
        a1 += xv * W[k*HID + c + 1];
    }
    *(__half2*)&out[(long)n*HID + c] = __floats2half2_rn(a0, a1);
}

// ---------------- fp32 64x64 tiled SGEMM (head GEMMs; high CTA count) ---------------
__global__ __launch_bounds__(128) void k_gemm64(
    const float* __restrict__ A, const float* __restrict__ B,
    const float* __restrict__ bias, float* __restrict__ C,
    int M, int Nn, int K)
{
    __shared__ float As[16][64];
    __shared__ float Bs[16][68];
    int tid  = threadIdx.x;           // 128
    int row0 = blockIdx.y * 64;
    int col0 = blockIdx.x * 64;
    int tr = tid >> 4, tc = tid & 15; // 8 x 16
    float acc[8][4] = {};
    for (int kt = 0; kt < K; kt += 16) {
        #pragma unroll
        for (int i = 0; i < 8; i++) {
            int e = tid + i*128;
            int m = e >> 4, k = e & 15;
            int gm = row0 + m, gk = kt + k;
            As[k][m] = (gm < M && gk < K) ? A[(long)gm*K + gk] : 0.f;
        }
        #pragma unroll
        for (int i = 0; i < 8; i++) {
            int e = tid + i*128;
            int k = e >> 6, n = e & 63;
            int gk = kt + k, gn = col0 + n;
            Bs[k][n] = (gk < K && gn < Nn) ? B[(long)gk*Nn + gn] : 0.f;
        }
        __syncthreads();
        #pragma unroll
        for (int k = 0; k < 16; k++) {
            float a[8], b[4];
            #pragma unroll
            for (int i = 0; i < 8; i++) a[i] = As[k][tr*8 + i];
            #pragma unroll
            for (int j = 0; j < 4; j++) b[j] = Bs[k][tc*4 + j];
            #pragma unroll
            for (int i = 0; i < 8; i++)
                #pragma unroll
                for (int j = 0; j < 4; j++)
                    acc[i][j] += a[i] * b[j];
        }
        __syncthreads();
    }
    #pragma unroll
    for (int i = 0; i < 8; i++) {
        int gm = row0 + tr*8 + i;
        if (gm >= M) continue;
        #pragma unroll
        for (int j = 0; j < 4; j++) {
            int gn = col0 + tc*4 + j;
            if (gn < Nn) C[(long)gm*Nn + gn] = acc[i][j] + (bias ? bias[gn] : 0.f);
        }
    }
}

// ---------------- fp16 mma.sync primitives -------------------------------------------
__device__ __forceinline__ void cp_async16(void* smem, const void* gmem, bool pred) {
    unsigned sa = (unsigned)__cvta_generic_to_shared(smem);
    int sz = pred ? 16 : 0;
    asm volatile("cp.async.cg.shared.global [%0], [%1], 16, %2;"
                 :: "r"(sa), "l"(gmem), "r"(sz));
}
__device__ __forceinline__ void ldsm_x4(uint32_t& r0, uint32_t& r1, uint32_t& r2,
                                        uint32_t& r3, const void* p) {
    uint32_t a = (uint32_t)__cvta_generic_to_shared(p);
    asm volatile("ldmatrix.sync.aligned.m8n8.x4.shared.b16 {%0,%1,%2,%3},[%4];"
                 : "=r"(r0), "=r"(r1), "=r"(r2), "=r"(r3) : "r"(a));
}
__device__ __forceinline__ void ldsm_x4t(uint32_t& r0, uint32_t& r1, uint32_t& r2,
                                         uint32_t& r3, const void* p) {
    uint32_t a = (uint32_t)__cvta_generic_to_shared(p);
    asm volatile("ldmatrix.sync.aligned.m8n8.x4.trans.shared.b16 {%0,%1,%2,%3},[%4];"
                 : "=r"(r0), "=r"(r1), "=r"(r2), "=r"(r3) : "r"(a));
}
__device__ __forceinline__ void mma_f16(float* c, const uint32_t* a, const uint32_t* b) {
    asm volatile("mma.sync.aligned.m16n8k16.row.col.f32.f16.f16.f32 "
        "{%0,%1,%2,%3},{%4,%5,%6,%7},{%8,%9},{%0,%1,%2,%3};"
        : "+f"(c[0]), "+f"(c[1]), "+f"(c[2]), "+f"(c[3])
        : "r"(a[0]), "r"(a[1]), "r"(a[2]), "r"(a[3]), "r"(b[0]), "r"(b[1]));
}

// ---------------- fp16 tensor GEMM: A[Mx512] @ Wcat[512xNCAT], 128x128 tiles ---------
__global__ __launch_bounds__(256, 2) void k_gemm_f16t(
    const __half* __restrict__ A, const __half* __restrict__ W,
    const float* __restrict__ bias,
    __half* __restrict__ basesO, float* __restrict__ combO, int M)
{
    extern __shared__ __align__(16) char smraw[];
    int tid = threadIdx.x, lane = tid & 31, warp = tid >> 5;
    int row0 = blockIdx.y * 128;
    int bx = blockIdx.x;
    int col0 = bx * 128;
    int mbase = (warp & 1) * 64, nbase = (warp >> 1) * 32;

    float acc[4][4][4] = {};
    const int KT = 16;

    #define ASP(s) ((__half*)(smraw + (s)*STG_BYTES))            // [128][40]
    #define BSP(s) ((__half*)(smraw + (s)*STG_BYTES + 10240))    // [32][136]

    #define LOADK(kt) do {                                                      \
        int st_ = (kt) & 3;                                                      \
        __half* as_ = ASP(st_);                                                  \
        __half* bs_ = BSP(st_);                                                  \
        _Pragma("unroll")                                                        \
        for (int p = 0; p < 2; p++) {                                            \
            int idx = tid + p*256;                                               \
            int r = idx >> 2, c8 = idx & 3;                                      \
            cp_async16(as_ + r*40 + c8*8,                                        \
                       A + (long)(row0 + r)*HID + (kt)*32 + c8*8,                \
                       (row0 + r) < M);                                          \
        }                                                                        \
        _Pragma("unroll")                                                        \
        for (int p = 0; p < 2; p++) {                                            \
            int idx = tid + p*256;                                               \
            int r = idx >> 4, c = idx & 15;                                      \
            bool pb = (col0 + c*8) < NCAT;                                       \
            cp_async16(bs_ + r*136 + c*8,                                        \
                       W + (long)((kt)*32 + r)*NCAT + col0 + c*8, pb);           \
        }                                                                        \
        asm volatile("cp.async.commit_group;");                                  \
    } while (0)

    LOADK(0); LOADK(1); LOADK(2);

    for (int kt = 0; kt < KT; kt++) {
        asm volatile("cp.async.wait_group 2;");
        __syncthreads();

        const __half* as = ASP(kt & 3);
        const __half* bs = BSP(kt & 3);
        #pragma unroll
        for (int ks = 0; ks < 2; ks++) {
            uint32_t a[4][4], b[4][2];
            #pragma unroll
            for (int mt = 0; mt < 4; mt++)
                ldsm_x4(a[mt][0], a[mt][1], a[mt][2], a[mt][3],
                        as + (mbase + mt*16 + (lane & 15))*40 + ks*16 + (lane >> 4)*8);
            #pragma unroll
            for (int np = 0; np < 2; np++)
                ldsm_x4t(b[np*2][0], b[np*2][1], b[np*2+1][0], b[np*2+1][1],
                         bs + (ks*16 + (lane & 15))*136 + nbase + np*16 + (lane >> 4)*8);
            #pragma unroll
            for (int mt = 0; mt < 4; mt++)
                #pragma unroll
                for (int nt = 0; nt < 4; nt++)
                    mma_f16(acc[mt][nt], a[mt], b[nt]);
        }

        if (kt + 3 < KT) LOADK(kt + 3);
        else             asm volatile("cp.async.commit_group;");
    }
    #undef LOADK
    #undef ASP
    #undef BSP

    if (bx < 4) {
        #pragma unroll
        for (int mt = 0; mt < 4; mt++) {
            int r0 = row0 + mbase + mt*16 + (lane >> 2);
            #pragma unroll
            for (int nt = 0; nt < 4; nt++) {
                int cn = col0 + nbase + nt*8 + (lane & 3)*2;
                if (r0 < M)
                    *(__half2*)&basesO[(long)r0*HID + cn] =
                        __floats2half2_rn(acc[mt][nt][0], acc[mt][nt][1]);
                if (r0 + 8 < M)
                    *(__half2*)&basesO[(long)(r0+8)*HID + cn] =
                        __floats2half2_rn(acc[mt][nt][2], acc[mt][nt][3]);
            }
        }
    } else {
        #pragma unroll
        for (int mt = 0; mt < 4; mt++) {
            int r0 = row0 + mbase + mt*16 + (lane >> 2);
            #pragma unroll
            for (int nt = 0; nt < 4; nt++) {
                int cc = (col0 - 512) + nbase + nt*8 + (lane & 3)*2;
                if (cc >= COMBC) continue;
                float b0 = bias[cc], b1 = bias[cc+1];
                if (r0 < M) {
                    combO[(long)r0*COMBP + cc]     = acc[mt][nt][0] + b0;
                    combO[(long)r0*COMBP + cc + 1] = acc[mt][nt][1] + b1;
                }
                if (r0 + 8 < M) {
                    combO[(long)(r0+8)*COMBP + cc]     = acc[mt][nt][2] + b0;
                    combO[(long)(r0+8)*COMBP + cc + 1] = acc[mt][nt][3] + b1;
                }
            }
        }
    }
}

// ---------------- weight prep: [k][Wb | Wc] fp16, no padding -------------------------
__global__ void k_prep_wcat(const float* __restrict__ Wb, const float* __restrict__ Wc) {
    long i = blockIdx.x * (long)blockDim.x + threadIdx.x;
    long tot = (long)LAYERS * HID * NCAT;
    if (i >= tot) return;
    int c = (int)(i % NCAT);
    long rl = i / NCAT;
    float v = (c < HID) ? Wb[rl*HID + c] : Wc[rl*COMBC + (c - HID)];
    d_wcat[i] = __float2half(v);
}

// ---------------- column stats: fp16 input, uint4 (8 halves/thread) ------------------
__global__ void k_colstats_partial_h(const __half* __restrict__ X, int M, int chunks,
                                     float* __restrict__ part) {
    int c8 = threadIdx.x;            // 64 threads, 8 cols each
    int ch = blockIdx.x;
    int rpc = (M + chunks - 1) / chunks;
    int r0 = ch * rpc, r1 = min(M, r0 + rpc);
    float s[8] = {}, ss[8] = {};
    const uint4* X8 = (const uint4*)X;
    for (int r = r0; r < r1; r++) {
        uint4 vp = X8[(long)r*(HID/8) + c8];
        const __half2* hp = (const __half2*)&vp;
        #pragma unroll
        for (int p = 0; p < 4; p++) {
            float2 f = __half22float2(hp[p]);
            s[p*2]   += f.x;     s[p*2+1]   += f.y;
            ss[p*2]  += f.x*f.x; ss[p*2+1]  += f.y*f.y;
        }
    }
    #pragma unroll
    for (int p = 0; p < 2; p++) {
        float4 v0 = make_float4(s[p*4], s[p*4+1], s[p*4+2], s[p*4+3]);
        float4 v1 = make_float4(ss[p*4], ss[p*4+1], ss[p*4+2], ss[p*4+3]);
        ((float4*)&part[(long)ch*2*HID])[c8*2 + p]       = v0;
        ((float4*)&part[(long)ch*2*HID + HID])[c8*2 + p] = v1;
    }
}

// ---------------- column stats: fp32 input (head path) ------------------------------
__global__ void k_colstats_partial(const float* __restrict__ X, int M, int C, int chunks,
                                   float* __restrict__ part) {
    int c = threadIdx.x;
    int ch = blockIdx.x;
    int rpc = (M + chunks - 1) / chunks;
    int r0 = ch * rpc, r1 = min(M, r0 + rpc);
    float s = 0.f, ss = 0.f;
    for (int r = r0; r < r1; r++) {
        float v = X[(long)r*C + c];
        s += v; ss += v*v;
    }
    part[(long)ch*2*C + c]     = s;
    part[(long)ch*2*C + C + c] = ss;
}
__global__ void k_colstats_final(const float* __restrict__ part, int chunks, int C, int M,
                                 const float* __restrict__ g, const float* __restrict__ b,
                                 float* __restrict__ scale, float* __restrict__ shift) {
    int c = blockIdx.x * blockDim.x + threadIdx.x;
    if (c >= C) return;
    float s = 0.f, ss = 0.f;
    for (int ch = 0; ch < chunks; ch++) {
        s  += part[(long)ch*2*C + c];
        ss += part[(long)ch*2*C + C + c];
    }
    float mean = s / (float)M;
    float var  = ss / (float)M - mean*mean;
    float sc   = g[c] * rsqrtf(var + EPSBN);
    scale[c] = sc;
    shift[c] = b[c] - mean*sc;
}

// ---------------- bn+relu+residual: fp16 t -> fp16 h, uint4 (8 halves/thread) -------
__global__ void k_bn_hh(const __half* __restrict__ X, const float* __restrict__ scale,
                        const float* __restrict__ shift, __half* __restrict__ h,
                        int total8, int residual) {
    int i = blockIdx.x * blockDim.x + threadIdx.x;
    if (i >= total8) return;
    int c = (i & (HID/8 - 1)) * 8;
    uint4 vp = ((const uint4*)X)[i];
    const __half2* xp = (const __half2*)&vp;
    float r[8];
    #pragma unroll
    for (int p = 0; p < 4; p++) {
        float2 f = __half22float2(xp[p]);
        r[p*2]   = fmaxf(fmaf(f.x, scale[c + p*2],     shift[c + p*2]),     0.f);
        r[p*2+1] = fmaxf(fmaf(f.y, scale[c + p*2 + 1], shift[c + p*2 + 1]), 0.f);
    }
    if (residual) {
        uint4 hp = ((const uint4*)h)[i];
        const __half2* hq = (const __half2*)&hp;
        #pragma unroll
        for (int p = 0; p < 4; p++) {
            float2 f = __half22float2(hq[p]);
            r[p*2] += f.x; r[p*2+1] += f.y;
        }
    }
    uint4 rp;
    __half2* rq = (__half2*)&rp;
    #pragma unroll
    for (int p = 0; p < 4; p++) rq[p] = __floats2half2_rn(r[p*2], r[p*2+1]);
    ((uint4*)h)[i] = rp;
}

// ---------------- bn+relu apply: fp32 (head path) ------------------------------------
__global__ void k_bn4(const float4* __restrict__ X, const float* __restrict__ scale,
                      const float* __restrict__ shift, float4* __restrict__ out,
                      int total4, int c4mask) {
    int i = blockIdx.x * blockDim.x + threadIdx.x;
    if (i >= total4) return;
    int c = (i & c4mask) * 4;
    float4 v = X[i];
    float4 r;
    r.x = fmaxf(fmaf(v.x, scale[c+0], shift[c+0]), 0.f);
    r.y = fmaxf(fmaf(v.y, scale[c+1], shift[c+1]), 0.f);
    r.z = fmaxf(fmaf(v.z, scale[c+2], shift[c+2]), 0.f);
    r.w = fmaxf(fmaf(v.w, scale[c+3], shift[c+3]), 0.f);
    out[i] = r;
}

// ---------------- CSR build --------------------------------------------------------
__global__ void k_csr_zero() {
    int i = blockIdx.x * blockDim.x + threadIdx.x;
    if (i < NN) { d_deg[i] = 0; d_cur[i] = 0; }
}
__global__ void k_csr_count(const int* __restrict__ edst) {
    int e = blockIdx.x * blockDim.x + threadIdx.x;
    if (e < EE) atomicAdd(&d_deg[edst[e]], 1);
}
#define SCB 200
#define SCCHUNK 500
__global__ void k_scan_part() {
    int b = blockIdx.x, t = threadIdx.x;
    int beg = b * SCCHUNK, endn = min(beg + SCCHUNK, NN);
    int s = 0;
    for (int i = beg + t; i < endn; i += 128) s += d_deg[i];
    __shared__ int sh[128];
    sh[t] = s; __syncthreads();
    for (int o = 64; o; o >>= 1) { if (t < o) sh[t] += sh[t+o]; __syncthreads(); }
    if (!t) d_bsum[b] = sh[0];
}
__global__ void k_scan_mid() {
    int run = 0;
    for (int i = 0; i < SCB; i++) { int v = d_bsum[i]; d_bsum[i] = run; run += v; }
}
__global__ void k_scan_write() {
    int b = blockIdx.x;
    int run = d_bsum[b];
    int beg = b * SCCHUNK, endn = min(beg + SCCHUNK, NN);
    for (int i = beg; i < endn; i++) { d_off[i] = run; run += d_deg[i]; }
    if (b == SCB - 1) d_off[NN] = run;
}
__global__ void k_csr_fill(const int* __restrict__ esrc, const int* __restrict__ edst) {
    int e = blockIdx.x * blockDim.x + threadIdx.x;
    if (e >= EE) return;
    int d = edst[e];
    int p = d_off[d] + atomicAdd(&d_cur[d], 1);
    d_csrc[p] = esrc[e];
}

// ---------------- fused aggregation + head-combine einsum (R9 staged form) ----------
__global__ __launch_bounds__(128) void k_agg(const __half* __restrict__ bases,
                                             const float* __restrict__ comb,
                                             __half* __restrict__ out) {
    int n = blockIdx.x;
    int tid = threadIdx.x;
    __shared__ float s_s[HID], s_m[HID], s_c[COMBC];
    __shared__ int   s_idx[128];

    const uint2* brow = (const uint2*)&bases[(long)n*HID];
    uint2 sp = brow[tid];
    float2 p0 = __half22float2(*(__half2*)&sp.x);
    float2 p1 = __half22float2(*(__half2*)&sp.y);
    float4 sv = make_float4(p0.x, p0.y, p1.x, p1.y);
    float4 mv = sv;

    int beg = d_off[n], endp = d_off[n+1];
    for (int base = beg; base < endp; base += 128) {
        int m = min(128, endp - base);
        if (tid < m) s_idx[tid] = d_csrc[base + tid];
        __syncthreads();
        for (int j = 0; j < m; j++) {
            uint2 vp = ((const uint2*)&bases[(long)s_idx[j]*HID])[tid];
            float2 a = __half22float2(*(__half2*)&vp.x);
            float2 b = __half22float2(*(__half2*)&vp.y);
            sv.x += a.x; sv.y += a.y; sv.z += b.x; sv.w += b.y;
            mv.x = fmaxf(mv.x, a.x); mv.y = fmaxf(mv.y, a.y);
            mv.z = fmaxf(mv.z, b.x); mv.w = fmaxf(mv.w, b.y);
        }
        __syncthreads();
    }

    ((float4*)s_s)[tid] = sv;
    ((float4*)s_m)[tid] = mv;
    if (tid < COMBC/4) ((float4*)s_c)[tid] = ((const float4*)&comb[(long)n*COMBP])[tid];
    __syncthreads();

    int q = tid * 4;
    float invc = 1.f / (float)(endp - beg + 1);
    int h = q >> 6;
    const float* w = &s_c[h * (NAGG*BASES)];
    float o[4] = {0.f, 0.f, 0.f, 0.f};
    #pragma unroll
    for (int b = 0; b < BASES; b++) {
        float ws = w[b];
        float wm = w[8 + b];
        float wx = w[16 + b];
        #pragma unroll
        for (int j = 0; j < 4; j++) {
            int f = (q + j) & 63;
            float s = s_s[b*FH + f];
            float x = s_m[b*FH + f];
            o[j] += ws * s + wm * s * invc + wx * x;
        }
    }
    uint2 rp;
    *(__half2*)&rp.x = __floats2half2_rn(o[0], o[1]);
    *(__half2*)&rp.y = __floats2half2_rn(o[2], o[3]);
    ((uint2*)&out[(long)n*HID])[tid] = rp;
}

// ---------------- graph mean pool (batch sorted, fp16 in, uint4) ---------------------
__global__ __launch_bounds__(64) void k_pool(const __half* __restrict__ h,
                                             const int* __restrict__ batch) {
    int g = blockIdx.x;
    int c8 = threadIdx.x;   // 64 threads x 8 cols
    int lo = 0, hi = NN;
    while (lo < hi) { int mid = (lo + hi) >> 1; if (batch[mid] < g) lo = mid + 1; else hi = mid; }
    int start = lo;
    hi = NN;
    while (lo < hi) { int mid = (lo + hi) >> 1; if (batch[mid] < g + 1) lo = mid + 1; else hi = mid; }
    int end = lo;
    float acc[8] = {};
    const uint4* h8 = (const uint4*)h;
    for (int i = start; i < end; i++) {
        uint4 vp = h8[(long)i*(HID/8) + c8];
        const __half2* hp = (const __half2*)&vp;
        #pragma unroll
        for (int p = 0; p < 4; p++) {
            float2 f = __half22float2(hp[p]);
            acc[p*2] += f.x; acc[p*2+1] += f.y;
        }
    }
    float inv = 1.f / (float)max(end - start, 1);
    #pragma unroll
    for (int p = 0; p < 2; p++) {
        float4 v = make_float4(acc[p*4]*inv, acc[p*4+1]*inv, acc[p*4+2]*inv, acc[p*4+3]*inv);
        ((float4*)&d_pool[(long)g*HID])[c8*2 + p] = v;
    }
}

// ---------------- concat + final head ----------------------------------------------
__global__ void k_concat(const float* __restrict__ z, const float* __restrict__ desc) {
    int i = blockIdx.x * blockDim.x + threadIdx.x;
    if (i >= GG*CAT) return;
    int g = i / CAT, c = i % CAT;
    d_zc[i] = (c < 128) ? z[g*128 + c] : desc[g*DESC + (c - 128)];
}
__global__ void k_final(const float* __restrict__ z, const float* __restrict__ W,
                        const float* __restrict__ b, float* __restrict__ out) {
    int g = blockIdx.x * 8 + (threadIdx.x >> 5);
    int lane = threadIdx.x & 31;
    if (g >= GG) return;
    float acc = 0.f;
    #pragma unroll
    for (int k = lane; k < 128; k += 32) acc += z[g*128 + k] * W[k];
    #pragma unroll
    for (int o = 16; o; o >>= 1) acc += __shfl_down_sync(0xffffffffu, acc, o);
    if (lane == 0) out[g] = acc + b[0];
}

// ---------------- host orchestration ------------------------------------------------
static inline void* sym(const void* s) { void* p = nullptr; cudaGetSymbolAddress(&p, s); return p; }

extern "C" void kernel_launch(void* const* d_in, const int* in_sizes, int n_in,
                              void* d_out, int out_size) {
    const float* x       = (const float*)d_in[0];
    const int*   ei      = (const int*)  d_in[1];
    const int*   batch   = (const int*)  d_in[2];
    const float* desc    = (const float*)d_in[3];
    const float* lin1_W  = (const float*)d_in[4];
    const float* norm1_g = (const float*)d_in[6];
    const float* norm1_b = (const float*)d_in[7];
    const float* Wb_all  = (const float*)d_in[8];
    const float* Wc_all  = (const float*)d_in[9];
    const float* bc_all  = (const float*)d_in[10];
    const float* ng_all  = (const float*)d_in[12];
    const float* nb_all  = (const float*)d_in[13];
    const float* mlp_W1  = (const float*)d_in[14];
    const float* mlp_g1  = (const float*)d_in[15];
    const float* mlp_b1  = (const float*)d_in[16];
    const float* mlp_W2  = (const float*)d_in[17];
    const float* mlp_g2  = (const float*)d_in[18];
    const float* mlp_b2  = (const float*)d_in[19];
    const float* lin2_W  = (const float*)d_in[20];
    const float* bn2_g   = (const float*)d_in[22];
    const float* bn2_b   = (const float*)d_in[23];
    const float* out_W   = (const float*)d_in[24];
    const float* out_b   = (const float*)d_in[25];
    float* out = (float*)d_out;

    const int* esrc = ei;
    const int* edst = ei + EE;

    __half* p_h     = (__half*)sym(d_h);
    __half* p_t     = (__half*)sym(d_t);
    __half* p_bases = (__half*)sym(d_bases);
    float*  p_comb  = (float*) sym(d_comb);
    float*  p_part  = (float*) sym(d_part);
    float*  p_scale = (float*) sym(d_scale);
    float*  p_shift = (float*) sym(d_shift);
    float*  p_pool  = (float*) sym(d_pool);
    float*  p_z1    = (float*) sym(d_z1);
    float*  p_z2    = (float*) sym(d_z2);
    float*  p_zc    = (float*) sym(d_zc);
    float*  p_z3    = (float*) sym(d_z3);
    __half* p_wcat  = (__half*)sym(d_wcat);

    const int NH8 = NN * (HID/8);

    cudaFuncSetAttribute(k_gemm_f16t,
                         cudaFuncAttributeMaxDynamicSharedMemorySize, G_SMEM);

    // ---- lin1 + BN chain first (k_bn_hh stays at profiled launch index 3) ----
    k_lin1<<<NN, 256>>>(x, lin1_W, p_t);                                        // 0
    k_colstats_partial_h<<<256, 64>>>(p_t, NN, 256, p_part);                    // 1
    k_colstats_final<<<2, 256>>>(p_part, 256, HID, NN, norm1_g, norm1_b,
                                 p_scale, p_shift);                             // 2
    k_bn_hh<<<(NH8 + 255)/256, 256>>>(p_t, p_scale, p_shift, p_h, NH8, 0);      // 3

    // ---- weight prep + CSR build ----
    {
        long nw = (long)LAYERS*HID*NCAT;
        k_prep_wcat<<<(int)((nw + 255)/256), 256>>>(Wb_all, Wc_all);
    }
    k_csr_zero <<<(NN + 255)/256, 256>>>();
    k_csr_count<<<(EE + 255)/256, 256>>>(edst);
    k_scan_part<<<SCB, 128>>>();
    k_scan_mid <<<1, 1>>>();
    k_scan_write<<<SCB, 1>>>();
    k_csr_fill <<<(EE + 255)/256, 256>>>(esrc, edst);

    // ---- EGConv layers ----
    dim3 grid_g(6, (NN + 127)/128);

    for (int l = 0; l < LAYERS; l++) {
        const __half* Wl = p_wcat + (long)l * HID * NCAT;
        const float*  bc = bc_all + (long)l * COMBC;
        const float*  ng = ng_all + (long)l * HID;
        const float*  nb = nb_all + (long)l * HID;

        k_gemm_f16t<<<grid_g, 256, G_SMEM>>>(p_h, Wl, bc, p_bases, p_comb, NN);
        k_agg<<<NN, 128>>>(p_bases, p_comb, p_t);
        k_colstats_partial_h<<<256, 64>>>(p_t, NN, 256, p_part);
        k_colstats_final<<<2, 256>>>(p_part, 256, HID, NN, ng, nb, p_scale, p_shift);
        k_bn_hh<<<(NH8 + 255)/256, 256>>>(p_t, p_scale, p_shift, p_h, NH8, 1);
    }

    // ---- pool ----
    k_pool<<<GG, 64>>>(p_h, batch);

    // ---- MLP head (64x64 tiles) ----
    dim3 g1(256/64, GG/64);
    k_gemm64<<<g1, 128>>>(p_pool, mlp_W1, nullptr, p_z1, GG, 256, HID);
    k_colstats_partial<<<64, 256>>>(p_z1, GG, 256, 64, p_part);
    k_colstats_final<<<1, 256>>>(p_part, 64, 256, GG, mlp_g1, mlp_b1, p_scale, p_shift);
    k_bn4<<<(GG*64 + 255)/256, 256>>>((const float4*)p_z1, p_scale, p_shift,
                                      (float4*)p_z1, GG*64, 63);

    dim3 g2(128/64, GG/64);
    k_gemm64<<<g2, 128>>>(p_z1, mlp_W2, nullptr, p_z2, GG, 128, 256);
    k_colstats_partial<<<64, 128>>>(p_z2, GG, 128, 64, p_part);
    k_colstats_final<<<1, 128>>>(p_part, 64, 128, GG, mlp_g2, mlp_b2, p_scale, p_shift);
    k_bn4<<<(GG*32 + 255)/256, 256>>>((const float4*)p_z2, p_scale, p_shift,
                                      (float4*)p_z2, GG*32, 31);

    k_concat<<<(GG*CAT + 255)/256, 256>>>(p_z2, desc);

    dim3 g3(128/64, GG/64);
    k_gemm64<<<g3, 128>>>(p_zc, lin2_W, nullptr, p_z3, GG, 128, CAT);
    k_colstats_partial<<<64, 128>>>(p_z3, GG, 128, 64, p_part);
    k_colstats_final<<<1, 128>>>(p_part, 64, 128, GG, bn2_g, bn2_b, p_scale, p_shift);
    k_bn4<<<(GG*32 + 255)/256, 256>>>((const float4*)p_z3, p_scale, p_shift,
                                      (float4*)p_z3, GG*32, 31);

    k_final<<<GG/8, 256>>>(p_z3, out_W, out_b, out);
}

// round 14
// speedup vs baseline: 1.1653x; 1.1653x over previous
#include <cuda_runtime.h>
#include <cuda_fp16.h>
#include <cstdint>

#define NN   100000
#define EE   200000
#define GG   4096
#define HID  512
#define LAYERS 4
#define HEADS 8
#define BASES 8
#define NAGG 3
#define FH   64
#define COMBC 192
#define COMBP 256
#define NCAT 704                   // 512 bases + 192 comb (no padding)
#define DESC 200
#define CAT  (128 + DESC)          // 328
#define EPSBN 1e-5f

// 4-stage GEMM smem: per stage As 128x40 halves (10240B) + Bs 32x136 halves (8704B)
#define STG_BYTES 18944
#define G_SMEM (4*STG_BYTES)       // 75776

// ---------------- scratch (static device allocations; no cudaMalloc) ----------------
__device__ __half d_h     [(long)NN*HID];      // residual stream, fp16
__device__ __half d_t     [(long)NN*HID];      // conv output (pre-BN), fp16
__device__ __half d_bases [(long)NN*HID];
__device__ float  d_comb  [(long)NN*COMBP];    // row stride 256, cols [0,192) valid
__device__ float  d_part  [256*2*HID];
__device__ float  d_scale [HID];
__device__ float  d_shift [HID];
__device__ float  d_pool  [(long)GG*HID];
__device__ float  d_z1    [(long)GG*256];
__device__ float  d_z2    [(long)GG*128];
__device__ float  d_zc    [(long)GG*CAT];
__device__ float  d_z3    [(long)GG*128];
__device__ __half d_wcat  [(long)LAYERS*HID*NCAT];   // [l][k][n]
// CSR
__device__ int d_deg [NN];
__device__ int d_off [NN+1];
__device__ int d_cur [NN];
__device__ int d_csrc[EE];
__device__ int d_bsum[256];

// ---------------- lin1 (writes fp16 t) ----------------------------------------------
__global__ void k_lin1(const float* __restrict__ x, const float* __restrict__ W,
                       __half* __restrict__ out) {
    int n = blockIdx.x;
    __shared__ float xs[27];
    int tid = threadIdx.x;   // 256
    if (tid < 27) xs[tid] = x[n*27 + tid];
    __syncthreads();
    int c = tid * 2;
    float a0 = 0.f, a1 = 0.f;
    #pragma unroll
    for (int k = 0; k < 27; k++) {
        float xv = xs[k];
        a0 += xv * W[k*HID + c];
        a1 += xv * W[k*HID + c + 1];
    }
    *(__half2*)&out[(long)n*HID + c] = __floats2half2_rn(a0, a1);
}

// ---------------- fp32 64x64 tiled SGEMM (head GEMMs; high CTA count) ---------------
__global__ __launch_bounds__(128) void k_gemm64(
    const float* __restrict__ A, const float* __restrict__ B,
    const float* __restrict__ bias, float* __restrict__ C,
    int M, int Nn, int K)
{
    __shared__ float As[16][64];
    __shared__ float Bs[16][68];
    int tid  = threadIdx.x;           // 128
    int row0 = blockIdx.y * 64;
    int col0 = blockIdx.x * 64;
    int tr = tid >> 4, tc = tid & 15; // 8 x 16
    float acc[8][4] = {};
    for (int kt = 0; kt < K; kt += 16) {
        #pragma unroll
        for (int i = 0; i < 8; i++) {
            int e = tid + i*128;
            int m = e >> 4, k = e & 15;
            int gm = row0 + m, gk = kt + k;
            As[k][m] = (gm < M && gk < K) ? A[(long)gm*K + gk] : 0.f;
        }
        #pragma unroll
        for (int i = 0; i < 8; i++) {
            int e = tid + i*128;
            int k = e >> 6, n = e & 63;
            int gk = kt + k, gn = col0 + n;
            Bs[k][n] = (gk < K && gn < Nn) ? B[(long)gk*Nn + gn] : 0.f;
        }
        __syncthreads();
        #pragma unroll
        for (int k = 0; k < 16; k++) {
            float a[8], b[4];
            #pragma unroll
            for (int i = 0; i < 8; i++) a[i] = As[k][tr*8 + i];
            #pragma unroll
            for (int j = 0; j < 4; j++) b[j] = Bs[k][tc*4 + j];
            #pragma unroll
            for (int i = 0; i < 8; i++)
                #pragma unroll
                for (int j = 0; j < 4; j++)
                    acc[i][j] += a[i] * b[j];
        }
        __syncthreads();
    }
    #pragma unroll
    for (int i = 0; i < 8; i++) {
        int gm = row0 + tr*8 + i;
        if (gm >= M) continue;
        #pragma unroll
        for (int j = 0; j < 4; j++) {
            int gn = col0 + tc*4 + j;
            if (gn < Nn) C[(long)gm*Nn + gn] = acc[i][j] + (bias ? bias[gn] : 0.f);
        }
    }
}

// ---------------- fp16 mma.sync primitives -------------------------------------------
__device__ __forceinline__ void cp_async16(void* smem, const void* gmem, bool pred) {
    unsigned sa = (unsigned)__cvta_generic_to_shared(smem);
    int sz = pred ? 16 : 0;
    asm volatile("cp.async.cg.shared.global [%0], [%1], 16, %2;"
                 :: "r"(sa), "l"(gmem), "r"(sz));
}
__device__ __forceinline__ void ldsm_x4(uint32_t& r0, uint32_t& r1, uint32_t& r2,
                                        uint32_t& r3, const void* p) {
    uint32_t a = (uint32_t)__cvta_generic_to_shared(p);
    asm volatile("ldmatrix.sync.aligned.m8n8.x4.shared.b16 {%0,%1,%2,%3},[%4];"
                 : "=r"(r0), "=r"(r1), "=r"(r2), "=r"(r3) : "r"(a));
}
__device__ __forceinline__ void ldsm_x4t(uint32_t& r0, uint32_t& r1, uint32_t& r2,
                                         uint32_t& r3, const void* p) {
    uint32_t a = (uint32_t)__cvta_generic_to_shared(p);
    asm volatile("ldmatrix.sync.aligned.m8n8.x4.trans.shared.b16 {%0,%1,%2,%3},[%4];"
                 : "=r"(r0), "=r"(r1), "=r"(r2), "=r"(r3) : "r"(a));
}
__device__ __forceinline__ void mma_f16(float* c, const uint32_t* a, const uint32_t* b) {
    asm volatile("mma.sync.aligned.m16n8k16.row.col.f32.f16.f16.f32 "
        "{%0,%1,%2,%3},{%4,%5,%6,%7},{%8,%9},{%0,%1,%2,%3};"
        : "+f"(c[0]), "+f"(c[1]), "+f"(c[2]), "+f"(c[3])
        : "r"(a[0]), "r"(a[1]), "r"(a[2]), "r"(a[3]), "r"(b[0]), "r"(b[1]));
}

// ---------------- fp16 tensor GEMM: A[Mx512] @ Wcat[512xNCAT], 128x128 tiles ---------
__global__ __launch_bounds__(256, 2) void k_gemm_f16t(
    const __half* __restrict__ A, const __half* __restrict__ W,
    const float* __restrict__ bias,
    __half* __restrict__ basesO, float* __restrict__ combO, int M)
{
    extern __shared__ __align__(16) char smraw[];
    int tid = threadIdx.x, lane = tid & 31, warp = tid >> 5;
    int row0 = blockIdx.y * 128;
    int bx = blockIdx.x;
    int col0 = bx * 128;
    int mbase = (warp & 1) * 64, nbase = (warp >> 1) * 32;

    float acc[4][4][4] = {};
    const int KT = 16;

    #define ASP(s) ((__half*)(smraw + (s)*STG_BYTES))            // [128][40]
    #define BSP(s) ((__half*)(smraw + (s)*STG_BYTES + 10240))    // [32][136]

    #define LOADK(kt) do {                                                      \
        int st_ = (kt) & 3;                                                      \
        __half* as_ = ASP(st_);                                                  \
        __half* bs_ = BSP(st_);                                                  \
        _Pragma("unroll")                                                        \
        for (int p = 0; p < 2; p++) {                                            \
            int idx = tid + p*256;                                               \
            int r = idx >> 2, c8 = idx & 3;                                      \
            cp_async16(as_ + r*40 + c8*8,                                        \
                       A + (long)(row0 + r)*HID + (kt)*32 + c8*8,                \
                       (row0 + r) < M);                                          \
        }                                                                        \
        _Pragma("unroll")                                                        \
        for (int p = 0; p < 2; p++) {                                            \
            int idx = tid + p*256;                                               \
            int r = idx >> 4, c = idx & 15;                                      \
            bool pb = (col0 + c*8) < NCAT;                                       \
            cp_async16(bs_ + r*136 + c*8,                                        \
                       W + (long)((kt)*32 + r)*NCAT + col0 + c*8, pb);           \
        }                                                                        \
        asm volatile("cp.async.commit_group;");                                  \
    } while (0)

    LOADK(0); LOADK(1); LOADK(2);

    for (int kt = 0; kt < KT; kt++) {
        asm volatile("cp.async.wait_group 2;");
        __syncthreads();

        const __half* as = ASP(kt & 3);
        const __half* bs = BSP(kt & 3);
        #pragma unroll
        for (int ks = 0; ks < 2; ks++) {
            uint32_t a[4][4], b[4][2];
            #pragma unroll
            for (int mt = 0; mt < 4; mt++)
                ldsm_x4(a[mt][0], a[mt][1], a[mt][2], a[mt][3],
                        as + (mbase + mt*16 + (lane & 15))*40 + ks*16 + (lane >> 4)*8);
            #pragma unroll
            for (int np = 0; np < 2; np++)
                ldsm_x4t(b[np*2][0], b[np*2][1], b[np*2+1][0], b[np*2+1][1],
                         bs + (ks*16 + (lane & 15))*136 + nbase + np*16 + (lane >> 4)*8);
            #pragma unroll
            for (int mt = 0; mt < 4; mt++)
                #pragma unroll
                for (int nt = 0; nt < 4; nt++)
                    mma_f16(acc[mt][nt], a[mt], b[nt]);
        }

        if (kt + 3 < KT) LOADK(kt + 3);
        else             asm volatile("cp.async.commit_group;");
    }
    #undef LOADK
    #undef ASP
    #undef BSP

    if (bx < 4) {
        #pragma unroll
        for (int mt = 0; mt < 4; mt++) {
            int r0 = row0 + mbase + mt*16 + (lane >> 2);
            #pragma unroll
            for (int nt = 0; nt < 4; nt++) {
                int cn = col0 + nbase + nt*8 + (lane & 3)*2;
                if (r0 < M)
                    *(__half2*)&basesO[(long)r0*HID + cn] =
                        __floats2half2_rn(acc[mt][nt][0], acc[mt][nt][1]);
                if (r0 + 8 < M)
                    *(__half2*)&basesO[(long)(r0+8)*HID + cn] =
                        __floats2half2_rn(acc[mt][nt][2], acc[mt][nt][3]);
            }
        }
    } else {
        #pragma unroll
        for (int mt = 0; mt < 4; mt++) {
            int r0 = row0 + mbase + mt*16 + (lane >> 2);
            #pragma unroll
            for (int nt = 0; nt < 4; nt++) {
                int cc = (col0 - 512) + nbase + nt*8 + (lane & 3)*2;
                if (cc >= COMBC) continue;
                float b0 = bias[cc], b1 = bias[cc+1];
                if (r0 < M) {
                    combO[(long)r0*COMBP + cc]     = acc[mt][nt][0] + b0;
                    combO[(long)r0*COMBP + cc + 1] = acc[mt][nt][1] + b1;
                }
                if (r0 + 8 < M) {
                    combO[(long)(r0+8)*COMBP + cc]     = acc[mt][nt][2] + b0;
                    combO[(long)(r0+8)*COMBP + cc + 1] = acc[mt][nt][3] + b1;
                }
            }
        }
    }
}

// ---------------- weight prep: [k][Wb | Wc] fp16, no padding -------------------------
__global__ void k_prep_wcat(const float* __restrict__ Wb, const float* __restrict__ Wc) {
    long i = blockIdx.x * (long)blockDim.x + threadIdx.x;
    long tot = (long)LAYERS * HID * NCAT;
    if (i >= tot) return;
    int c = (int)(i % NCAT);
    long rl = i / NCAT;
    float v = (c < HID) ? Wb[rl*HID + c] : Wc[rl*COMBC + (c - HID)];
    d_wcat[i] = __float2half(v);
}

// ---------------- column stats: fp16 input (R12 uint2 form) --------------------------
__global__ void k_colstats_partial_h(const __half* __restrict__ X, int M, int chunks,
                                     float* __restrict__ part) {
    int c4 = threadIdx.x;
    int ch = blockIdx.x;
    int rpc = (M + chunks - 1) / chunks;
    int r0 = ch * rpc, r1 = min(M, r0 + rpc);
    float4 s = make_float4(0.f,0.f,0.f,0.f), ss = s;
    const uint2* X4 = (const uint2*)X;
    for (int r = r0; r < r1; r++) {
        uint2 vp = X4[(long)r*(HID/4) + c4];
        float2 a = __half22float2(*(__half2*)&vp.x);
        float2 b = __half22float2(*(__half2*)&vp.y);
        s.x += a.x; s.y += a.y; s.z += b.x; s.w += b.y;
        ss.x += a.x*a.x; ss.y += a.y*a.y; ss.z += b.x*b.x; ss.w += b.y*b.y;
    }
    ((float4*)&part[(long)ch*2*HID])[c4]       = s;
    ((float4*)&part[(long)ch*2*HID + HID])[c4] = ss;
}

// ---------------- column stats: fp32 input (head path) ------------------------------
__global__ void k_colstats_partial(const float* __restrict__ X, int M, int C, int chunks,
                                   float* __restrict__ part) {
    int c = threadIdx.x;
    int ch = blockIdx.x;
    int rpc = (M + chunks - 1) / chunks;
    int r0 = ch * rpc, r1 = min(M, r0 + rpc);
    float s = 0.f, ss = 0.f;
    for (int r = r0; r < r1; r++) {
        float v = X[(long)r*C + c];
        s += v; ss += v*v;
    }
    part[(long)ch*2*C + c]     = s;
    part[(long)ch*2*C + C + c] = ss;
}
__global__ void k_colstats_final(const float* __restrict__ part, int chunks, int C, int M,
                                 const float* __restrict__ g, const float* __restrict__ b,
                                 float* __restrict__ scale, float* __restrict__ shift) {
    int c = blockIdx.x * blockDim.x + threadIdx.x;
    if (c >= C) return;
    float s = 0.f, ss = 0.f;
    for (int ch = 0; ch < chunks; ch++) {
        s  += part[(long)ch*2*C + c];
        ss += part[(long)ch*2*C + C + c];
    }
    float mean = s / (float)M;
    float var  = ss / (float)M - mean*mean;
    float sc   = g[c] * rsqrtf(var + EPSBN);
    scale[c] = sc;
    shift[c] = b[c] - mean*sc;
}

// ---------------- bn+relu+residual: fp16 t -> fp16 h (R12 uint2 form) ---------------
__global__ void k_bn_hh(const __half* __restrict__ X, const float* __restrict__ scale,
                        const float* __restrict__ shift, __half* __restrict__ h,
                        int total4, int residual) {
    int i = blockIdx.x * blockDim.x + threadIdx.x;
    if (i >= total4) return;
    int c = (i & (HID/4 - 1)) * 4;
    uint2 vp = ((const uint2*)X)[i];
    float2 a = __half22float2(*(__half2*)&vp.x);
    float2 bq = __half22float2(*(__half2*)&vp.y);
    float r0 = fmaxf(fmaf(a.x,  scale[c+0], shift[c+0]), 0.f);
    float r1 = fmaxf(fmaf(a.y,  scale[c+1], shift[c+1]), 0.f);
    float r2 = fmaxf(fmaf(bq.x, scale[c+2], shift[c+2]), 0.f);
    float r3 = fmaxf(fmaf(bq.y, scale[c+3], shift[c+3]), 0.f);
    if (residual) {
        uint2 hp = ((const uint2*)h)[i];
        float2 h0 = __half22float2(*(__half2*)&hp.x);
        float2 h1 = __half22float2(*(__half2*)&hp.y);
        r0 += h0.x; r1 += h0.y; r2 += h1.x; r3 += h1.y;
    }
    uint2 rp;
    *(__half2*)&rp.x = __floats2half2_rn(r0, r1);
    *(__half2*)&rp.y = __floats2half2_rn(r2, r3);
    ((uint2*)h)[i] = rp;
}

// ---------------- bn+relu apply: fp32 (head path) ------------------------------------
__global__ void k_bn4(const float4* __restrict__ X, const float* __restrict__ scale,
                      const float* __restrict__ shift, float4* __restrict__ out,
                      int total4, int c4mask) {
    int i = blockIdx.x * blockDim.x + threadIdx.x;
    if (i >= total4) return;
    int c = (i & c4mask) * 4;
    float4 v = X[i];
    float4 r;
    r.x = fmaxf(fmaf(v.x, scale[c+0], shift[c+0]), 0.f);
    r.y = fmaxf(fmaf(v.y, scale[c+1], shift[c+1]), 0.f);
    r.z = fmaxf(fmaf(v.z, scale[c+2], shift[c+2]), 0.f);
    r.w = fmaxf(fmaf(v.w, scale[c+3], shift[c+3]), 0.f);
    out[i] = r;
}

// ---------------- CSR build --------------------------------------------------------
__global__ void k_csr_zero() {
    int i = blockIdx.x * blockDim.x + threadIdx.x;
    if (i < NN) { d_deg[i] = 0; d_cur[i] = 0; }
}
__global__ void k_csr_count(const int* __restrict__ edst) {
    int e = blockIdx.x * blockDim.x + threadIdx.x;
    if (e < EE) atomicAdd(&d_deg[edst[e]], 1);
}
#define SCB 200
#define SCCHUNK 500
__global__ void k_scan_part() {
    int b = blockIdx.x, t = threadIdx.x;
    int beg = b * SCCHUNK, endn = min(beg + SCCHUNK, NN);
    int s = 0;
    for (int i = beg + t; i < endn; i += 128) s += d_deg[i];
    __shared__ int sh[128];
    sh[t] = s; __syncthreads();
    for (int o = 64; o; o >>= 1) { if (t < o) sh[t] += sh[t+o]; __syncthreads(); }
    if (!t) d_bsum[b] = sh[0];
}
__global__ void k_scan_mid() {
    int run = 0;
    for (int i = 0; i < SCB; i++) { int v = d_bsum[i]; d_bsum[i] = run; run += v; }
}
__global__ void k_scan_write() {
    int b = blockIdx.x;
    int run = d_bsum[b];
    int beg = b * SCCHUNK, endn = min(beg + SCCHUNK, NN);
    for (int i = beg; i < endn; i++) { d_off[i] = run; run += d_deg[i]; }
    if (b == SCB - 1) d_off[NN] = run;
}
__global__ void k_csr_fill(const int* __restrict__ esrc, const int* __restrict__ edst) {
    int e = blockIdx.x * blockDim.x + threadIdx.x;
    if (e >= EE) return;
    int d = edst[e];
    int p = d_off[d] + atomicAdd(&d_cur[d], 1);
    d_csrc[p] = esrc[e];
}

// ---------------- fused aggregation + head-combine einsum (comb hoisted) ------------
__global__ __launch_bounds__(128) void k_agg(const __half* __restrict__ bases,
                                             const float* __restrict__ comb,
                                             __half* __restrict__ out) {
    int n = blockIdx.x;
    int tid = threadIdx.x;
    __shared__ float s_s[HID], s_m[HID], s_c[COMBC];
    __shared__ int   s_idx[128];

    // hoist comb load: overlaps the gather loop's latency
    float cpre[4];
    bool has_c = tid < COMBC/4;
    if (has_c) {
        float4 cv = ((const float4*)&comb[(long)n*COMBP])[tid];
        cpre[0] = cv.x; cpre[1] = cv.y; cpre[2] = cv.z; cpre[3] = cv.w;
    }

    const uint2* brow = (const uint2*)&bases[(long)n*HID];
    uint2 sp = brow[tid];
    float2 p0 = __half22float2(*(__half2*)&sp.x);
    float2 p1 = __half22float2(*(__half2*)&sp.y);
    float4 sv = make_float4(p0.x, p0.y, p1.x, p1.y);
    float4 mv = sv;

    int beg = d_off[n], endp = d_off[n+1];
    for (int base = beg; base < endp; base += 128) {
        int m = min(128, endp - base);
        if (tid < m) s_idx[tid] = d_csrc[base + tid];
        __syncthreads();
        for (int j = 0; j < m; j++) {
            uint2 vp = ((const uint2*)&bases[(long)s_idx[j]*HID])[tid];
            float2 a = __half22float2(*(__half2*)&vp.x);
            float2 b = __half22float2(*(__half2*)&vp.y);
            sv.x += a.x; sv.y += a.y; sv.z += b.x; sv.w += b.y;
            mv.x = fmaxf(mv.x, a.x); mv.y = fmaxf(mv.y, a.y);
            mv.z = fmaxf(mv.z, b.x); mv.w = fmaxf(mv.w, b.y);
        }
        __syncthreads();
    }

    ((float4*)s_s)[tid] = sv;
    ((float4*)s_m)[tid] = mv;
    if (has_c) {
        float4 cv; cv.x = cpre[0]; cv.y = cpre[1]; cv.z = cpre[2]; cv.w = cpre[3];
        ((float4*)s_c)[tid] = cv;
    }
    __syncthreads();

    int q = tid * 4;
    float invc = 1.f / (float)(endp - beg + 1);
    int h = q >> 6;
    const float* w = &s_c[h * (NAGG*BASES)];
    float o[4] = {0.f, 0.f, 0.f, 0.f};
    #pragma unroll
    for (int b = 0; b < BASES; b++) {
        float ws = w[b];
        float wm = w[8 + b];
        float wx = w[16 + b];
        #pragma unroll
        for (int j = 0; j < 4; j++) {
            int f = (q + j) & 63;
            float s = s_s[b*FH + f];
            float x = s_m[b*FH + f];
            o[j] += ws * s + wm * s * invc + wx * x;
        }
    }
    uint2 rp;
    *(__half2*)&rp.x = __floats2half2_rn(o[0], o[1]);
    *(__half2*)&rp.y = __floats2half2_rn(o[2], o[3]);
    ((uint2*)&out[(long)n*HID])[tid] = rp;
}

// ---------------- graph mean pool (batch sorted, fp16 in, R12 form) ------------------
__global__ __launch_bounds__(128) void k_pool(const __half* __restrict__ h,
                                              const int* __restrict__ batch) {
    int g = blockIdx.x;
    int c4 = threadIdx.x;
    int lo = 0, hi = NN;
    while (lo < hi) { int mid = (lo + hi) >> 1; if (batch[mid] < g) lo = mid + 1; else hi = mid; }
    int start = lo;
    hi = NN;
    while (lo < hi) { int mid = (lo + hi) >> 1; if (batch[mid] < g + 1) lo = mid + 1; else hi = mid; }
    int end = lo;
    float4 acc = make_float4(0.f,0.f,0.f,0.f);
    const uint2* h4 = (const uint2*)h;
    for (int i = start; i < end; i++) {
        uint2 vp = h4[(long)i*(HID/4) + c4];
        float2 a = __half22float2(*(__half2*)&vp.x);
        float2 b = __half22float2(*(__half2*)&vp.y);
        acc.x += a.x; acc.y += a.y; acc.z += b.x; acc.w += b.y;
    }
    float inv = 1.f / (float)max(end - start, 1);
    acc.x *= inv; acc.y *= inv; acc.z *= inv; acc.w *= inv;
    ((float4*)&d_pool[(long)g*HID])[c4] = acc;
}

// ---------------- concat + final head ----------------------------------------------
__global__ void k_concat(const float* __restrict__ z, const float* __restrict__ desc) {
    int i = blockIdx.x * blockDim.x + threadIdx.x;
    if (i >= GG*CAT) return;
    int g = i / CAT, c = i % CAT;
    d_zc[i] = (c < 128) ? z[g*128 + c] : desc[g*DESC + (c - 128)];
}
__global__ void k_final(const float* __restrict__ z, const float* __restrict__ W,
                        const float* __restrict__ b, float* __restrict__ out) {
    int g = blockIdx.x * 8 + (threadIdx.x >> 5);
    int lane = threadIdx.x & 31;
    if (g >= GG) return;
    float acc = 0.f;
    #pragma unroll
    for (int k = lane; k < 128; k += 32) acc += z[g*128 + k] * W[k];
    #pragma unroll
    for (int o = 16; o; o >>= 1) acc += __shfl_down_sync(0xffffffffu, acc, o);
    if (lane == 0) out[g] = acc + b[0];
}

// ---------------- host orchestration ------------------------------------------------
static inline void* sym(const void* s) { void* p = nullptr; cudaGetSymbolAddress(&p, s); return p; }

extern "C" void kernel_launch(void* const* d_in, const int* in_sizes, int n_in,
                              void* d_out, int out_size) {
    const float* x       = (const float*)d_in[0];
    const int*   ei      = (const int*)  d_in[1];
    const int*   batch   = (const int*)  d_in[2];
    const float* desc    = (const float*)d_in[3];
    const float* lin1_W  = (const float*)d_in[4];
    const float* norm1_g = (const float*)d_in[6];
    const float* norm1_b = (const float*)d_in[7];
    const float* Wb_all  = (const float*)d_in[8];
    const float* Wc_all  = (const float*)d_in[9];
    const float* bc_all  = (const float*)d_in[10];
    const float* ng_all  = (const float*)d_in[12];
    const float* nb_all  = (const float*)d_in[13];
    const float* mlp_W1  = (const float*)d_in[14];
    const float* mlp_g1  = (const float*)d_in[15];
    const float* mlp_b1  = (const float*)d_in[16];
    const float* mlp_W2  = (const float*)d_in[17];
    const float* mlp_g2  = (const float*)d_in[18];
    const float* mlp_b2  = (const float*)d_in[19];
    const float* lin2_W  = (const float*)d_in[20];
    const float* bn2_g   = (const float*)d_in[22];
    const float* bn2_b   = (const float*)d_in[23];
    const float* out_W   = (const float*)d_in[24];
    const float* out_b   = (const float*)d_in[25];
    float* out = (float*)d_out;

    const int* esrc = ei;
    const int* edst = ei + EE;

    __half* p_h     = (__half*)sym(d_h);
    __half* p_t     = (__half*)sym(d_t);
    __half* p_bases = (__half*)sym(d_bases);
    float*  p_comb  = (float*) sym(d_comb);
    float*  p_part  = (float*) sym(d_part);
    float*  p_scale = (float*) sym(d_scale);
    float*  p_shift = (float*) sym(d_shift);
    float*  p_pool  = (float*) sym(d_pool);
    float*  p_z1    = (float*) sym(d_z1);
    float*  p_z2    = (float*) sym(d_z2);
    float*  p_zc    = (float*) sym(d_zc);
    float*  p_z3    = (float*) sym(d_z3);
    __half* p_wcat  = (__half*)sym(d_wcat);

    const int NH4 = NN * (HID/4);

    cudaFuncSetAttribute(k_gemm_f16t,
                         cudaFuncAttributeMaxDynamicSharedMemorySize, G_SMEM);

    // ---- lin1 + BN chain first (k_bn_hh stays at profiled launch index 3) ----
    k_lin1<<<NN, 256>>>(x, lin1_W, p_t);                                        // 0
    k_colstats_partial_h<<<256, 128>>>(p_t, NN, 256, p_part);                   // 1
    k_colstats_final<<<2, 256>>>(p_part, 256, HID, NN, norm1_g, norm1_b,
                                 p_scale, p_shift);                             // 2
    k_bn_hh<<<(NH4 + 255)/256, 256>>>(p_t, p_scale, p_shift, p_h, NH4, 0);      // 3

    // ---- weight prep + CSR build ----
    {
        long nw = (long)LAYERS*HID*NCAT;
        k_prep_wcat<<<(int)((nw + 255)/256), 256>>>(Wb_all, Wc_all);
    }
    k_csr_zero <<<(NN + 255)/256, 256>>>();
    k_csr_count<<<(EE + 255)/256, 256>>>(edst);
    k_scan_part<<<SCB, 128>>>();
    k_scan_mid <<<1, 1>>>();
    k_scan_write<<<SCB, 1>>>();
    k_csr_fill <<<(EE + 255)/256, 256>>>(esrc, edst);

    // ---- EGConv layers ----
    dim3 grid_g(6, (NN + 127)/128);

    for (int l = 0; l < LAYERS; l++) {
        const __half* Wl = p_wcat + (long)l * HID * NCAT;
        const float*  bc = bc_all + (long)l * COMBC;
        const float*  ng = ng_all + (long)l * HID;
        const float*  nb = nb_all + (long)l * HID;

        k_gemm_f16t<<<grid_g, 256, G_SMEM>>>(p_h, Wl, bc, p_bases, p_comb, NN);
        k_agg<<<NN, 128>>>(p_bases, p_comb, p_t);
        k_colstats_partial_h<<<256, 128>>>(p_t, NN, 256, p_part);
        k_colstats_final<<<2, 256>>>(p_part, 256, HID, NN, ng, nb, p_scale, p_shift);
        k_bn_hh<<<(NH4 + 255)/256, 256>>>(p_t, p_scale, p_shift, p_h, NH4, 1);
    }

    // ---- pool ----
    k_pool<<<GG, 128>>>(p_h, batch);

    // ---- MLP head (64x64 tiles) ----
    dim3 g1(256/64, GG/64);
    k_gemm64<<<g1, 128>>>(p_pool, mlp_W1, nullptr, p_z1, GG, 256, HID);
    k_colstats_partial<<<64, 256>>>(p_z1, GG, 256, 64, p_part);
    k_colstats_final<<<1, 256>>>(p_part, 64, 256, GG, mlp_g1, mlp_b1, p_scale, p_shift);
    k_bn4<<<(GG*64 + 255)/256, 256>>>((const float4*)p_z1, p_scale, p_shift,
                                      (float4*)p_z1, GG*64, 63);

    dim3 g2(128/64, GG/64);
    k_gemm64<<<g2, 128>>>(p_z1, mlp_W2, nullptr, p_z2, GG, 128, 256);
    k_colstats_partial<<<64, 128>>>(p_z2, GG, 128, 64, p_part);
    k_colstats_final<<<1, 128>>>(p_part, 64, 128, GG, mlp_g2, mlp_b2, p_scale, p_shift);
    k_bn4<<<(GG*32 + 255)/256, 256>>>((const float4*)p_z2, p_scale, p_shift,
                                      (float4*)p_z2, GG*32, 31);

    k_concat<<<(GG*CAT + 255)/256, 256>>>(p_z2, desc);

    dim3 g3(128/64, GG/64);
    k_gemm64<<<g3, 128>>>(p_zc, lin2_W, nullptr, p_z3, GG, 128, CAT);
    k_colstats_partial<<<64, 128>>>(p_z3, GG, 128, 64, p_part);
    k_colstats_final<<<1, 128>>>(p_part, 64, 128, GG, bn2_g, bn2_b, p_scale, p_shift);
    k_bn4<<<(GG*32 + 255)/256, 256>>>((const float4*)p_z3, p_scale, p_shift,
                                      (float4*)p_z3, GG*32, 31);

    k_final<<<GG/8, 256>>>(p_z3, out_W, out_b, out);
}

// round 15
// speedup vs baseline: 1.1856x; 1.0175x over previous
#include <cuda_runtime.h>
#include <cuda_fp16.h>
#include <cstdint>

#define NN   100000
#define EE   200000
#define GG   4096
#define HID  512
#define LAYERS 4
#define HEADS 8
#define BASES 8
#define NAGG 3
#define FH   64
#define COMBC 192
#define COMBP 256
#define NCAT 704                   // 512 bases + 192 comb (no padding)
#define DESC 200
#define CAT  (128 + DESC)          // 328
#define EPSBN 1e-5f

// 4-stage GEMM smem: per stage As 128x40 halves (10240B) + Bs 32x136 halves (8704B)
#define STG_BYTES 18944
#define G_SMEM (4*STG_BYTES)       // 75776

// ---------------- scratch (static device allocations; no cudaMalloc) ----------------
__device__ __half d_h     [(long)NN*HID];      // residual stream, fp16
__device__ __half d_t     [(long)NN*HID];      // conv output (pre-BN), fp16
__device__ __half d_bases [(long)NN*HID];
__device__ __half d_comb  [(long)NN*COMBP];    // fp16; row stride 256, cols [0,192) valid
__device__ float  d_part  [256*2*HID];
__device__ float  d_scale [HID];
__device__ float  d_shift [HID];
__device__ float  d_pool  [(long)GG*HID];
__device__ float  d_z1    [(long)GG*256];
__device__ float  d_z2    [(long)GG*128];
__device__ float  d_zc    [(long)GG*CAT];
__device__ float  d_z3    [(long)GG*128];
__device__ __half d_wcat  [(long)LAYERS*HID*NCAT];   // [l][k][n]
// CSR
__device__ int d_deg [NN];
__device__ int d_off [NN+1];
__device__ int d_cur [NN];
__device__ int d_csrc[EE];
__device__ int d_bsum[256];

// ---------------- lin1 (writes fp16 t) ----------------------------------------------
__global__ void k_lin1(const float* __restrict__ x, const float* __restrict__ W,
                       __half* __restrict__ out) {
    int n = blockIdx.x;
    __shared__ float xs[27];
    int tid = threadIdx.x;   // 256
    if (tid < 27) xs[tid] = x[n*27 + tid];
    __syncthreads();
    int c = tid * 2;
    float a0 = 0.f, a1 = 0.f;
    #pragma unroll
    for (int k = 0; k < 27; k++) {
        float xv = xs[k];
        a0 += xv * W[k*HID + c];
        a1 += xv * W[k*HID + c + 1];
    }
    *(__half2*)&out[(long)n*HID + c] = __floats2half2_rn(a0, a1);
}

// ---------------- fp32 64x64 tiled SGEMM (head GEMMs; high CTA count) ---------------
__global__ __launch_bounds__(128) void k_gemm64(
    const float* __restrict__ A, const float* __restrict__ B,
    const float* __restrict__ bias, float* __restrict__ C,
    int M, int Nn, int K)
{
    __shared__ float As[16][64];
    __shared__ float Bs[16][68];
    int tid  = threadIdx.x;           // 128
    int row0 = blockIdx.y * 64;
    int col0 = blockIdx.x * 64;
    int tr = tid >> 4, tc = tid & 15; // 8 x 16
    float acc[8][4] = {};
    for (int kt = 0; kt < K; kt += 16) {
        #pragma unroll
        for (int i = 0; i < 8; i++) {
            int e = tid + i*128;
            int m = e >> 4, k = e & 15;
            int gm = row0 + m, gk = kt + k;
            As[k][m] = (gm < M && gk < K) ? A[(long)gm*K + gk] : 0.f;
        }
        #pragma unroll
        for (int i = 0; i < 8; i++) {
            int e = tid + i*128;
            int k = e >> 6, n = e & 63;
            int gk = kt + k, gn = col0 + n;
            Bs[k][n] = (gk < K && gn < Nn) ? B[(long)gk*Nn + gn] : 0.f;
        }
        __syncthreads();
        #pragma unroll
        for (int k = 0; k < 16; k++) {
            float a[8], b[4];
            #pragma unroll
            for (int i = 0; i < 8; i++) a[i] = As[k][tr*8 + i];
            #pragma unroll
            for (int j = 0; j < 4; j++) b[j] = Bs[k][tc*4 + j];
            #pragma unroll
            for (int i = 0; i < 8; i++)
                #pragma unroll
                for (int j = 0; j < 4; j++)
                    acc[i][j] += a[i] * b[j];
        }
        __syncthreads();
    }
    #pragma unroll
    for (int i = 0; i < 8; i++) {
        int gm = row0 + tr*8 + i;
        if (gm >= M) continue;
        #pragma unroll
        for (int j = 0; j < 4; j++) {
            int gn = col0 + tc*4 + j;
            if (gn < Nn) C[(long)gm*Nn + gn] = acc[i][j] + (bias ? bias[gn] : 0.f);
        }
    }
}

// ---------------- fp16 mma.sync primitives -------------------------------------------
__device__ __forceinline__ void cp_async16(void* smem, const void* gmem, bool pred) {
    unsigned sa = (unsigned)__cvta_generic_to_shared(smem);
    int sz = pred ? 16 : 0;
    asm volatile("cp.async.cg.shared.global [%0], [%1], 16, %2;"
                 :: "r"(sa), "l"(gmem), "r"(sz));
}
__device__ __forceinline__ void ldsm_x4(uint32_t& r0, uint32_t& r1, uint32_t& r2,
                                        uint32_t& r3, const void* p) {
    uint32_t a = (uint32_t)__cvta_generic_to_shared(p);
    asm volatile("ldmatrix.sync.aligned.m8n8.x4.shared.b16 {%0,%1,%2,%3},[%4];"
                 : "=r"(r0), "=r"(r1), "=r"(r2), "=r"(r3) : "r"(a));
}
__device__ __forceinline__ void ldsm_x4t(uint32_t& r0, uint32_t& r1, uint32_t& r2,
                                         uint32_t& r3, const void* p) {
    uint32_t a = (uint32_t)__cvta_generic_to_shared(p);
    asm volatile("ldmatrix.sync.aligned.m8n8.x4.trans.shared.b16 {%0,%1,%2,%3},[%4];"
                 : "=r"(r0), "=r"(r1), "=r"(r2), "=r"(r3) : "r"(a));
}
__device__ __forceinline__ void mma_f16(float* c, const uint32_t* a, const uint32_t* b) {
    asm volatile("mma.sync.aligned.m16n8k16.row.col.f32.f16.f16.f32 "
        "{%0,%1,%2,%3},{%4,%5,%6,%7},{%8,%9},{%0,%1,%2,%3};"
        : "+f"(c[0]), "+f"(c[1]), "+f"(c[2]), "+f"(c[3])
        : "r"(a[0]), "r"(a[1]), "r"(a[2]), "r"(a[3]), "r"(b[0]), "r"(b[1]));
}

// ---------------- fp16 tensor GEMM: A[Mx512] @ Wcat[512xNCAT], 128x128 tiles ---------
__global__ __launch_bounds__(256, 2) void k_gemm_f16t(
    const __half* __restrict__ A, const __half* __restrict__ W,
    const float* __restrict__ bias,
    __half* __restrict__ basesO, __half* __restrict__ combO, int M)
{
    extern __shared__ __align__(16) char smraw[];
    int tid = threadIdx.x, lane = tid & 31, warp = tid >> 5;
    int row0 = blockIdx.y * 128;
    int bx = blockIdx.x;
    int col0 = bx * 128;
    int mbase = (warp & 1) * 64, nbase = (warp >> 1) * 32;

    float acc[4][4][4] = {};
    const int KT = 16;

    #define ASP(s) ((__half*)(smraw + (s)*STG_BYTES))            // [128][40]
    #define BSP(s) ((__half*)(smraw + (s)*STG_BYTES + 10240))    // [32][136]

    #define LOADK(kt) do {                                                      \
        int st_ = (kt) & 3;                                                      \
        __half* as_ = ASP(st_);                                                  \
        __half* bs_ = BSP(st_);                                                  \
        _Pragma("unroll")                                                        \
        for (int p = 0; p < 2; p++) {                                            \
            int idx = tid + p*256;                                               \
            int r = idx >> 2, c8 = idx & 3;                                      \
            cp_async16(as_ + r*40 + c8*8,                                        \
                       A + (long)(row0 + r)*HID + (kt)*32 + c8*8,                \
                       (row0 + r) < M);                                          \
        }                                                                        \
        _Pragma("unroll")                                                        \
        for (int p = 0; p < 2; p++) {                                            \
            int idx = tid + p*256;                                               \
            int r = idx >> 4, c = idx & 15;                                      \
            bool pb = (col0 + c*8) < NCAT;                                       \
            cp_async16(bs_ + r*136 + c*8,                                        \
                       W + (long)((kt)*32 + r)*NCAT + col0 + c*8, pb);           \
        }                                                                        \
        asm volatile("cp.async.commit_group;");                                  \
    } while (0)

    LOADK(0); LOADK(1); LOADK(2);

    for (int kt = 0; kt < KT; kt++) {
        asm volatile("cp.async.wait_group 2;");
        __syncthreads();

        const __half* as = ASP(kt & 3);
        const __half* bs = BSP(kt & 3);
        #pragma unroll
        for (int ks = 0; ks < 2; ks++) {
            uint32_t a[4][4], b[4][2];
            #pragma unroll
            for (int mt = 0; mt < 4; mt++)
                ldsm_x4(a[mt][0], a[mt][1], a[mt][2], a[mt][3],
                        as + (mbase + mt*16 + (lane & 15))*40 + ks*16 + (lane >> 4)*8);
            #pragma unroll
            for (int np = 0; np < 2; np++)
                ldsm_x4t(b[np*2][0], b[np*2][1], b[np*2+1][0], b[np*2+1][1],
                         bs + (ks*16 + (lane & 15))*136 + nbase + np*16 + (lane >> 4)*8);
            #pragma unroll
            for (int mt = 0; mt < 4; mt++)
                #pragma unroll
                for (int nt = 0; nt < 4; nt++)
                    mma_f16(acc[mt][nt], a[mt], b[nt]);
        }

        if (kt + 3 < KT) LOADK(kt + 3);
        else             asm volatile("cp.async.commit_group;");
    }
    #undef LOADK
    #undef ASP
    #undef BSP

    if (bx < 4) {
        #pragma unroll
        for (int mt = 0; mt < 4; mt++) {
            int r0 = row0 + mbase + mt*16 + (lane >> 2);
            #pragma unroll
            for (int nt = 0; nt < 4; nt++) {
                int cn = col0 + nbase + nt*8 + (lane & 3)*2;
                if (r0 < M)
                    *(__half2*)&basesO[(long)r0*HID + cn] =
                        __floats2half2_rn(acc[mt][nt][0], acc[mt][nt][1]);
                if (r0 + 8 < M)
                    *(__half2*)&basesO[(long)(r0+8)*HID + cn] =
                        __floats2half2_rn(acc[mt][nt][2], acc[mt][nt][3]);
            }
        }
    } else {
        #pragma unroll
        for (int mt = 0; mt < 4; mt++) {
            int r0 = row0 + mbase + mt*16 + (lane >> 2);
            #pragma unroll
            for (int nt = 0; nt < 4; nt++) {
                int cc = (col0 - 512) + nbase + nt*8 + (lane & 3)*2;
                if (cc >= COMBC) continue;
                float b0 = bias[cc], b1 = bias[cc+1];
                if (r0 < M)
                    *(__half2*)&combO[(long)r0*COMBP + cc] =
                        __floats2half2_rn(acc[mt][nt][0] + b0, acc[mt][nt][1] + b1);
                if (r0 + 8 < M)
                    *(__half2*)&combO[(long)(r0+8)*COMBP + cc] =
                        __floats2half2_rn(acc[mt][nt][2] + b0, acc[mt][nt][3] + b1);
            }
        }
    }
}

// ---------------- weight prep: [k][Wb | Wc] fp16, no padding -------------------------
__global__ void k_prep_wcat(const float* __restrict__ Wb, const float* __restrict__ Wc) {
    long i = blockIdx.x * (long)blockDim.x + threadIdx.x;
    long tot = (long)LAYERS * HID * NCAT;
    if (i >= tot) return;
    int c = (int)(i % NCAT);
    long rl = i / NCAT;
    float v = (c < HID) ? Wb[rl*HID + c] : Wc[rl*COMBC + (c - HID)];
    d_wcat[i] = __float2half(v);
}

// ---------------- column stats: fp16 input (uint2 form) ------------------------------
__global__ void k_colstats_partial_h(const __half* __restrict__ X, int M, int chunks,
                                     float* __restrict__ part) {
    int c4 = threadIdx.x;
    int ch = blockIdx.x;
    int rpc = (M + chunks - 1) / chunks;
    int r0 = ch * rpc, r1 = min(M, r0 + rpc);
    float4 s = make_float4(0.f,0.f,0.f,0.f), ss = s;
    const uint2* X4 = (const uint2*)X;
    for (int r = r0; r < r1; r++) {
        uint2 vp = X4[(long)r*(HID/4) + c4];
        float2 a = __half22float2(*(__half2*)&vp.x);
        float2 b = __half22float2(*(__half2*)&vp.y);
        s.x += a.x; s.y += a.y; s.z += b.x; s.w += b.y;
        ss.x += a.x*a.x; ss.y += a.y*a.y; ss.z += b.x*b.x; ss.w += b.y*b.y;
    }
    ((float4*)&part[(long)ch*2*HID])[c4]       = s;
    ((float4*)&part[(long)ch*2*HID + HID])[c4] = ss;
}

// ---------------- column stats: fp32 input (head path) ------------------------------
__global__ void k_colstats_partial(const float* __restrict__ X, int M, int C, int chunks,
                                   float* __restrict__ part) {
    int c = threadIdx.x;
    int ch = blockIdx.x;
    int rpc = (M + chunks - 1) / chunks;
    int r0 = ch * rpc, r1 = min(M, r0 + rpc);
    float s = 0.f, ss = 0.f;
    for (int r = r0; r < r1; r++) {
        float v = X[(long)r*C + c];
        s += v; ss += v*v;
    }
    part[(long)ch*2*C + c]     = s;
    part[(long)ch*2*C + C + c] = ss;
}
__global__ void k_colstats_final(const float* __restrict__ part, int chunks, int C, int M,
                                 const float* __restrict__ g, const float* __restrict__ b,
                                 float* __restrict__ scale, float* __restrict__ shift) {
    int c = blockIdx.x * blockDim.x + threadIdx.x;
    if (c >= C) return;
    float s = 0.f, ss = 0.f;
    for (int ch = 0; ch < chunks; ch++) {
        s  += part[(long)ch*2*C + c];
        ss += part[(long)ch*2*C + C + c];
    }
    float mean = s / (float)M;
    float var  = ss / (float)M - mean*mean;
    float sc   = g[c] * rsqrtf(var + EPSBN);
    scale[c] = sc;
    shift[c] = b[c] - mean*sc;
}

// ---------------- bn+relu+residual: fp16 t -> fp16 h (uint2 form) -------------------
__global__ void k_bn_hh(const __half* __restrict__ X, const float* __restrict__ scale,
                        const float* __restrict__ shift, __half* __restrict__ h,
                        int total4, int residual) {
    int i = blockIdx.x * blockDim.x + threadIdx.x;
    if (i >= total4) return;
    int c = (i & (HID/4 - 1)) * 4;
    uint2 vp = ((const uint2*)X)[i];
    float2 a = __half22float2(*(__half2*)&vp.x);
    float2 bq = __half22float2(*(__half2*)&vp.y);
    float r0 = fmaxf(fmaf(a.x,  scale[c+0], shift[c+0]), 0.f);
    float r1 = fmaxf(fmaf(a.y,  scale[c+1], shift[c+1]), 0.f);
    float r2 = fmaxf(fmaf(bq.x, scale[c+2], shift[c+2]), 0.f);
    float r3 = fmaxf(fmaf(bq.y, scale[c+3], shift[c+3]), 0.f);
    if (residual) {
        uint2 hp = ((const uint2*)h)[i];
        float2 h0 = __half22float2(*(__half2*)&hp.x);
        float2 h1 = __half22float2(*(__half2*)&hp.y);
        r0 += h0.x; r1 += h0.y; r2 += h1.x; r3 += h1.y;
    }
    uint2 rp;
    *(__half2*)&rp.x = __floats2half2_rn(r0, r1);
    *(__half2*)&rp.y = __floats2half2_rn(r2, r3);
    ((uint2*)h)[i] = rp;
}

// ---------------- bn+relu apply: fp32 (head path) ------------------------------------
__global__ void k_bn4(const float4* __restrict__ X, const float* __restrict__ scale,
                      const float* __restrict__ shift, float4* __restrict__ out,
                      int total4, int c4mask) {
    int i = blockIdx.x * blockDim.x + threadIdx.x;
    if (i >= total4) return;
    int c = (i & c4mask) * 4;
    float4 v = X[i];
    float4 r;
    r.x = fmaxf(fmaf(v.x, scale[c+0], shift[c+0]), 0.f);
    r.y = fmaxf(fmaf(v.y, scale[c+1], shift[c+1]), 0.f);
    r.z = fmaxf(fmaf(v.z, scale[c+2], shift[c+2]), 0.f);
    r.w = fmaxf(fmaf(v.w, scale[c+3], shift[c+3]), 0.f);
    out[i] = r;
}

// ---------------- CSR build --------------------------------------------------------
__global__ void k_csr_zero() {
    int i = blockIdx.x * blockDim.x + threadIdx.x;
    if (i < NN) { d_deg[i] = 0; d_cur[i] = 0; }
}
__global__ void k_csr_count(const int* __restrict__ edst) {
    int e = blockIdx.x * blockDim.x + threadIdx.x;
    if (e < EE) atomicAdd(&d_deg[edst[e]], 1);
}
#define SCB 200
#define SCCHUNK 500
__global__ void k_scan_part() {
    int b = blockIdx.x, t = threadIdx.x;
    int beg = b * SCCHUNK, endn = min(beg + SCCHUNK, NN);
    int s = 0;
    for (int i = beg + t; i < endn; i += 128) s += d_deg[i];
    __shared__ int sh[128];
    sh[t] = s; __syncthreads();
    for (int o = 64; o; o >>= 1) { if (t < o) sh[t] += sh[t+o]; __syncthreads(); }
    if (!t) d_bsum[b] = sh[0];
}
__global__ void k_scan_mid() {
    int run = 0;
    for (int i = 0; i < SCB; i++) { int v = d_bsum[i]; d_bsum[i] = run; run += v; }
}
__global__ void k_scan_write() {
    int b = blockIdx.x;
    int run = d_bsum[b];
    int beg = b * SCCHUNK, endn = min(beg + SCCHUNK, NN);
    for (int i = beg; i < endn; i++) { d_off[i] = run; run += d_deg[i]; }
    if (b == SCB - 1) d_off[NN] = run;
}
__global__ void k_csr_fill(const int* __restrict__ esrc, const int* __restrict__ edst) {
    int e = blockIdx.x * blockDim.x + threadIdx.x;
    if (e >= EE) return;
    int d = edst[e];
    int p = d_off[d] + atomicAdd(&d_cur[d], 1);
    d_csrc[p] = esrc[e];
}

// ---------------- fused aggregation + head-combine einsum (fp16 comb hoisted) -------
__global__ __launch_bounds__(128) void k_agg(const __half* __restrict__ bases,
                                             const __half* __restrict__ comb,
                                             __half* __restrict__ out) {
    int n = blockIdx.x;
    int tid = threadIdx.x;
    __shared__ float s_s[HID], s_m[HID], s_c[COMBC];
    __shared__ int   s_idx[128];

    // hoist comb load (fp16, 4 vals = uint2): overlaps the gather loop's latency
    float cpre[4];
    bool has_c = tid < COMBC/4;
    if (has_c) {
        uint2 cv = ((const uint2*)&comb[(long)n*COMBP])[tid];
        float2 c0 = __half22float2(*(__half2*)&cv.x);
        float2 c1 = __half22float2(*(__half2*)&cv.y);
        cpre[0] = c0.x; cpre[1] = c0.y; cpre[2] = c1.x; cpre[3] = c1.y;
    }

    const uint2* brow = (const uint2*)&bases[(long)n*HID];
    uint2 sp = brow[tid];
    float2 p0 = __half22float2(*(__half2*)&sp.x);
    float2 p1 = __half22float2(*(__half2*)&sp.y);
    float4 sv = make_float4(p0.x, p0.y, p1.x, p1.y);
    float4 mv = sv;

    int beg = d_off[n], endp = d_off[n+1];
    for (int base = beg; base < endp; base += 128) {
        int m = min(128, endp - base);
        if (tid < m) s_idx[tid] = d_csrc[base + tid];
        __syncthreads();
        for (int j = 0; j < m; j++) {
            uint2 vp = ((const uint2*)&bases[(long)s_idx[j]*HID])[tid];
            float2 a = __half22float2(*(__half2*)&vp.x);
            float2 b = __half22float2(*(__half2*)&vp.y);
            sv.x += a.x; sv.y += a.y; sv.z += b.x; sv.w += b.y;
            mv.x = fmaxf(mv.x, a.x); mv.y = fmaxf(mv.y, a.y);
            mv.z = fmaxf(mv.z, b.x); mv.w = fmaxf(mv.w, b.y);
        }
        __syncthreads();
    }

    ((float4*)s_s)[tid] = sv;
    ((float4*)s_m)[tid] = mv;
    if (has_c) {
        float4 cv; cv.x = cpre[0]; cv.y = cpre[1]; cv.z = cpre[2]; cv.w = cpre[3];
        ((float4*)s_c)[tid] = cv;
    }
    __syncthreads();

    int q = tid * 4;
    float invc = 1.f / (float)(endp - beg + 1);
    int h = q >> 6;
    const float* w = &s_c[h * (NAGG*BASES)];
    float o[4] = {0.f, 0.f, 0.f, 0.f};
    #pragma unroll
    for (int b = 0; b < BASES; b++) {
        float ws = w[b];
        float wm = w[8 + b];
        float wx = w[16 + b];
        #pragma unroll
        for (int j = 0; j < 4; j++) {
            int f = (q + j) & 63;
            float s = s_s[b*FH + f];
            float x = s_m[b*FH + f];
            o[j] += ws * s + wm * s * invc + wx * x;
        }
    }
    uint2 rp;
    *(__half2*)&rp.x = __floats2half2_rn(o[0], o[1]);
    *(__half2*)&rp.y = __floats2half2_rn(o[2], o[3]);
    ((uint2*)&out[(long)n*HID])[tid] = rp;
}

// ---------------- graph mean pool (batch sorted, fp16 in) ----------------------------
__global__ __launch_bounds__(128) void k_pool(const __half* __restrict__ h,
                                              const int* __restrict__ batch) {
    int g = blockIdx.x;
    int c4 = threadIdx.x;
    int lo = 0, hi = NN;
    while (lo < hi) { int mid = (lo + hi) >> 1; if (batch[mid] < g) lo = mid + 1; else hi = mid; }
    int start = lo;
    hi = NN;
    while (lo < hi) { int mid = (lo + hi) >> 1; if (batch[mid] < g + 1) lo = mid + 1; else hi = mid; }
    int end = lo;
    float4 acc = make_float4(0.f,0.f,0.f,0.f);
    const uint2* h4 = (const uint2*)h;
    for (int i = start; i < end; i++) {
        uint2 vp = h4[(long)i*(HID/4) + c4];
        float2 a = __half22float2(*(__half2*)&vp.x);
        float2 b = __half22float2(*(__half2*)&vp.y);
        acc.x += a.x; acc.y += a.y; acc.z += b.x; acc.w += b.y;
    }
    float inv = 1.f / (float)max(end - start, 1);
    acc.x *= inv; acc.y *= inv; acc.z *= inv; acc.w *= inv;
    ((float4*)&d_pool[(long)g*HID])[c4] = acc;
}

// ---------------- concat + final head ----------------------------------------------
__global__ void k_concat(const float* __restrict__ z, const float* __restrict__ desc) {
    int i = blockIdx.x * blockDim.x + threadIdx.x;
    if (i >= GG*CAT) return;
    int g = i / CAT, c = i % CAT;
    d_zc[i] = (c < 128) ? z[g*128 + c] : desc[g*DESC + (c - 128)];
}
__global__ void k_final(const float* __restrict__ z, const float* __restrict__ W,
                        const float* __restrict__ b, float* __restrict__ out) {
    int g = blockIdx.x * 8 + (threadIdx.x >> 5);
    int lane = threadIdx.x & 31;
    if (g >= GG) return;
    float acc = 0.f;
    #pragma unroll
    for (int k = lane; k < 128; k += 32) acc += z[g*128 + k] * W[k];
    #pragma unroll
    for (int o = 16; o; o >>= 1) acc += __shfl_down_sync(0xffffffffu, acc, o);
    if (lane == 0) out[g] = acc + b[0];
}

// ---------------- host orchestration ------------------------------------------------
static inline void* sym(const void* s) { void* p = nullptr; cudaGetSymbolAddress(&p, s); return p; }

extern "C" void kernel_launch(void* const* d_in, const int* in_sizes, int n_in,
                              void* d_out, int out_size) {
    const float* x       = (const float*)d_in[0];
    const int*   ei      = (const int*)  d_in[1];
    const int*   batch   = (const int*)  d_in[2];
    const float* desc    = (const float*)d_in[3];
    const float* lin1_W  = (const float*)d_in[4];
    const float* norm1_g = (const float*)d_in[6];
    const float* norm1_b = (const float*)d_in[7];
    const float* Wb_all  = (const float*)d_in[8];
    const float* Wc_all  = (const float*)d_in[9];
    const float* bc_all  = (const float*)d_in[10];
    const float* ng_all  = (const float*)d_in[12];
    const float* nb_all  = (const float*)d_in[13];
    const float* mlp_W1  = (const float*)d_in[14];
    const float* mlp_g1  = (const float*)d_in[15];
    const float* mlp_b1  = (const float*)d_in[16];
    const float* mlp_W2  = (const float*)d_in[17];
    const float* mlp_g2  = (const float*)d_in[18];
    const float* mlp_b2  = (const float*)d_in[19];
    const float* lin2_W  = (const float*)d_in[20];
    const float* bn2_g   = (const float*)d_in[22];
    const float* bn2_b   = (const float*)d_in[23];
    const float* out_W   = (const float*)d_in[24];
    const float* out_b   = (const float*)d_in[25];
    float* out = (float*)d_out;

    const int* esrc = ei;
    const int* edst = ei + EE;

    __half* p_h     = (__half*)sym(d_h);
    __half* p_t     = (__half*)sym(d_t);
    __half* p_bases = (__half*)sym(d_bases);
    __half* p_comb  = (__half*)sym(d_comb);
    float*  p_part  = (float*) sym(d_part);
    float*  p_scale = (float*) sym(d_scale);
    float*  p_shift = (float*) sym(d_shift);
    float*  p_pool  = (float*) sym(d_pool);
    float*  p_z1    = (float*) sym(d_z1);
    float*  p_z2    = (float*) sym(d_z2);
    float*  p_zc    = (float*) sym(d_zc);
    float*  p_z3    = (float*) sym(d_z3);
    __half* p_wcat  = (__half*)sym(d_wcat);

    const int NH4 = NN * (HID/4);

    cudaFuncSetAttribute(k_gemm_f16t,
                         cudaFuncAttributeMaxDynamicSharedMemorySize, G_SMEM);

    // ---- lin1 + BN chain first (k_bn_hh stays at profiled launch index 3) ----
    k_lin1<<<NN, 256>>>(x, lin1_W, p_t);                                        // 0
    k_colstats_partial_h<<<256, 128>>>(p_t, NN, 256, p_part);                   // 1
    k_colstats_final<<<2, 256>>>(p_part, 256, HID, NN, norm1_g, norm1_b,
                                 p_scale, p_shift);                             // 2
    k_bn_hh<<<(NH4 + 255)/256, 256>>>(p_t, p_scale, p_shift, p_h, NH4, 0);      // 3

    // ---- weight prep + CSR build ----
    {
        long nw = (long)LAYERS*HID*NCAT;
        k_prep_wcat<<<(int)((nw + 255)/256), 256>>>(Wb_all, Wc_all);
    }
    k_csr_zero <<<(NN + 255)/256, 256>>>();
    k_csr_count<<<(EE + 255)/256, 256>>>(edst);
    k_scan_part<<<SCB, 128>>>();
    k_scan_mid <<<1, 1>>>();
    k_scan_write<<<SCB, 1>>>();
    k_csr_fill <<<(EE + 255)/256, 256>>>(esrc, edst);

    // ---- EGConv layers ----
    dim3 grid_g(6, (NN + 127)/128);

    for (int l = 0; l < LAYERS; l++) {
        const __half* Wl = p_wcat + (long)l * HID * NCAT;
        const float*  bc = bc_all + (long)l * COMBC;
        const float*  ng = ng_all + (long)l * HID;
        const float*  nb = nb_all + (long)l * HID;

        k_gemm_f16t<<<grid_g, 256, G_SMEM>>>(p_h, Wl, bc, p_bases, p_comb, NN);
        k_agg<<<NN, 128>>>(p_bases, p_comb, p_t);
        k_colstats_partial_h<<<256, 128>>>(p_t, NN, 256, p_part);
        k_colstats_final<<<2, 256>>>(p_part, 256, HID, NN, ng, nb, p_scale, p_shift);
        k_bn_hh<<<(NH4 + 255)/256, 256>>>(p_t, p_scale, p_shift, p_h, NH4, 1);
    }

    // ---- pool ----
    k_pool<<<GG, 128>>>(p_h, batch);

    // ---- MLP head (64x64 tiles) ----
    dim3 g1(256/64, GG/64);
    k_gemm64<<<g1, 128>>>(p_pool, mlp_W1, nullptr, p_z1, GG, 256, HID);
    k_colstats_partial<<<64, 256>>>(p_z1, GG, 256, 64, p_part);
    k_colstats_final<<<1, 256>>>(p_part, 64, 256, GG, mlp_g1, mlp_b1, p_scale, p_shift);
    k_bn4<<<(GG*64 + 255)/256, 256>>>((const float4*)p_z1, p_scale, p_shift,
                                      (float4*)p_z1, GG*64, 63);

    dim3 g2(128/64, GG/64);
    k_gemm64<<<g2, 128>>>(p_z1, mlp_W2, nullptr, p_z2, GG, 128, 256);
    k_colstats_partial<<<64, 128>>>(p_z2, GG, 128, 64, p_part);
    k_colstats_final<<<1, 128>>>(p_part, 64, 128, GG, mlp_g2, mlp_b2, p_scale, p_shift);
    k_bn4<<<(GG*32 + 255)/256, 256>>>((const float4*)p_z2, p_scale, p_shift,
                                      (float4*)p_z2, GG*32, 31);

    k_concat<<<(GG*CAT + 255)/256, 256>>>(p_z2, desc);

    dim3 g3(128/64, GG/64);
    k_gemm64<<<g3, 128>>>(p_zc, lin2_W, nullptr, p_z3, GG, 128, CAT);
    k_colstats_partial<<<64, 128>>>(p_z3, GG, 128, 64, p_part);
    k_colstats_final<<<1, 128>>>(p_part, 64, 128, GG, bn2_g, bn2_b, p_scale, p_shift);
    k_bn4<<<(GG*32 + 255)/256, 256>>>((const float4*)p_z3, p_scale, p_shift,
                                      (float4*)p_z3, GG*32, 31);

    k_final<<<GG/8, 256>>>(p_z3, out_W, out_b, out);
}